// round 4
// baseline (speedup 1.0000x reference)
#include <cuda_runtime.h>
#include <cuda_bf16.h>
#include <cstdint>
#include <cstddef>

#define BDIM 8192
#define CDIM 4096
#define NQKV 12288

__device__ __align__(1024) float g_qkv[(size_t)BDIM * NQKV];
__device__ __align__(1024) float g_attn[(size_t)BDIM * CDIM];

__device__ __forceinline__ uint32_t smem_u32(const void* p) {
    uint32_t a;
    asm("{ .reg .u64 t; cvta.to.shared.u64 t, %1; cvt.u32.u64 %0, t; }" : "=r"(a) : "l"(p));
    return a;
}
__device__ __forceinline__ uint32_t rna(float x) {
    uint32_t u; asm("cvt.rna.tf32.f32 %0, %1;" : "=r"(u) : "f"(x)); return u;
}
__device__ __forceinline__ void mma8(float* c, const uint32_t* a, const uint32_t* b) {
    asm volatile("mma.sync.aligned.m16n8k8.row.col.f32.tf32.tf32.f32 "
        "{%0,%1,%2,%3}, {%4,%5,%6,%7}, {%8,%9}, {%0,%1,%2,%3};"
        : "+f"(c[0]), "+f"(c[1]), "+f"(c[2]), "+f"(c[3])
        : "r"(a[0]), "r"(a[1]), "r"(a[2]), "r"(a[3]), "r"(b[0]), "r"(b[1]));
}
__device__ __forceinline__ void cpasync16(uint32_t dst, const float* src) {
    asm volatile("cp.async.cg.shared.global [%0], [%1], 16;" :: "r"(dst), "l"(src));
}
#define CP_COMMIT asm volatile("cp.async.commit_group;" ::: "memory")
#define CP_WAIT0  asm volatile("cp.async.wait_group 0;" ::: "memory")

// C[m,n] = sum_k A[m,k]*B[n,k] (+bias[n]); A,B row-major K=4096
__global__ void __launch_bounds__(256) gemm_tf32(
    const float* __restrict__ A, const float* __restrict__ B,
    float* __restrict__ C, const float* __restrict__ bias, int ntot)
{
    __shared__ __align__(16) float sA[2][2560], sB[2][2560];
    const int tid = threadIdx.x, lane = tid & 31, wid = tid >> 5;
    const int gid = lane >> 2, tig = lane & 3;
    const int wm = wid & 1, wn = wid >> 1;
    const int m0 = blockIdx.y * 128, n0 = blockIdx.x * 128;

    float acc[4][4][4] = {};

    // prologue stage 0
    {
        uint32_t da = smem_u32(sA[0]), db = smem_u32(sB[0]);
        #pragma unroll
        for (int i = tid; i < 512; i += 256) {
            int r = i >> 2, c = i & 3;
            cpasync16(da + (r*20 + c*4)*4, A + (size_t)(m0+r)*4096 + c*4);
            cpasync16(db + (r*20 + c*4)*4, B + (size_t)(n0+r)*4096 + c*4);
        }
        CP_COMMIT;
    }

    #pragma unroll 1
    for (int kt = 0; kt < 256; kt++) {
        CP_WAIT0;
        __syncthreads();
        if (kt + 1 < 256) {
            int nb = (kt + 1) & 1;
            uint32_t da = smem_u32(sA[nb]), db = smem_u32(sB[nb]);
            #pragma unroll
            for (int i = tid; i < 512; i += 256) {
                int r = i >> 2, c = i & 3;
                cpasync16(da + (r*20 + c*4)*4, A + (size_t)(m0+r)*4096 + (kt+1)*16 + c*4);
                cpasync16(db + (r*20 + c*4)*4, B + (size_t)(n0+r)*4096 + (kt+1)*16 + c*4);
            }
            CP_COMMIT;
        }
        const float* As = sA[kt & 1];
        const float* Bs = sB[kt & 1];
        #pragma unroll
        for (int ks = 0; ks < 2; ks++) {
            const int k = ks * 8;
            uint32_t a[4][4], bf[4][2];
            #pragma unroll
            for (int mt = 0; mt < 4; mt++) {
                int r = wm*64 + mt*16 + gid;
                a[mt][0] = rna(As[r*20 + k + tig]);
                a[mt][1] = rna(As[(r+8)*20 + k + tig]);
                a[mt][2] = rna(As[r*20 + k + tig + 4]);
                a[mt][3] = rna(As[(r+8)*20 + k + tig + 4]);
            }
            #pragma unroll
            for (int nt = 0; nt < 4; nt++) {
                int n = wn*32 + nt*8 + gid;
                bf[nt][0] = rna(Bs[n*20 + k + tig]);
                bf[nt][1] = rna(Bs[n*20 + k + tig + 4]);
            }
            #pragma unroll
            for (int mt = 0; mt < 4; mt++)
                #pragma unroll
                for (int nt = 0; nt < 4; nt++)
                    mma8(acc[mt][nt], a[mt], bf[nt]);
        }
    }

    #pragma unroll
    for (int mt = 0; mt < 4; mt++) {
        #pragma unroll
        for (int nt = 0; nt < 4; nt++) {
            int row = m0 + wm*64 + mt*16 + gid;
            int col = n0 + wn*32 + nt*8 + tig*2;
            float b0 = 0.f, b1 = 0.f;
            if (bias) { b0 = bias[col]; b1 = bias[col + 1]; }
            float2 v0 = make_float2(acc[mt][nt][0] + b0, acc[mt][nt][1] + b1);
            float2 v1 = make_float2(acc[mt][nt][2] + b0, acc[mt][nt][3] + b1);
            *(float2*)(C + (size_t)row * ntot + col) = v0;
            *(float2*)(C + (size_t)(row + 8) * ntot + col) = v1;
        }
    }
}

// per-token 32x32 head-mixing attention. qkv[b] = [3][32 heads][128], out col = d*32+h
#define RS 132
__global__ void __launch_bounds__(128) attn_kernel(
    const float* __restrict__ qkv, float* __restrict__ attn)
{
    extern __shared__ float sm[];
    const int b = blockIdx.x;
    const int t = threadIdx.x, w = t >> 5, lane = t & 31;

    const float4* src4 = (const float4*)(qkv + (size_t)b * NQKV);
    for (int i = t; i < 3072; i += 128) {
        int mat = i >> 10, rm = i & 1023;
        *(float4*)(sm + mat*(32*RS) + (rm >> 5)*RS + (rm & 31)*4) = src4[i];
    }
    __syncthreads();

    float* sq = sm;
    float* sk = sm + 32*RS;
    float* sv = sm + 64*RS;
    float* ss = sm + 96*RS;   // 32 x stride 33
    const float scale = 0.08838834764831845f; // 1/sqrt(128)

    {
        float a8[8] = {};
        #pragma unroll
        for (int ch = 0; ch < 4; ch++) {
            float4 q[8];
            #pragma unroll
            for (int j = 0; j < 8; j++)
                q[j] = *(const float4*)(sq + lane*RS + ch*32 + j*4);
            #pragma unroll
            for (int g0 = 0; g0 < 8; g0++) {
                const float* kr = sk + (w*8 + g0)*RS + ch*32;
                #pragma unroll
                for (int j = 0; j < 8; j++) {
                    float4 k4 = *(const float4*)(kr + j*4);
                    a8[g0] += q[j].x*k4.x + q[j].y*k4.y + q[j].z*k4.z + q[j].w*k4.w;
                }
            }
        }
        #pragma unroll
        for (int g0 = 0; g0 < 8; g0++)
            ss[lane*33 + w*8 + g0] = a8[g0] * scale;
    }
    __syncthreads();

    if (w == 0) {
        float mx = -1e30f;
        #pragma unroll
        for (int g = 0; g < 32; g++) mx = fmaxf(mx, ss[lane*33 + g]);
        float sum = 0.f;
        #pragma unroll
        for (int g = 0; g < 32; g++) {
            float e = __expf(ss[lane*33 + g] - mx);
            ss[lane*33 + g] = e; sum += e;
        }
        float inv = 1.f / sum;
        #pragma unroll
        for (int g = 0; g < 32; g++) ss[lane*33 + g] *= inv;
    }
    __syncthreads();

    {
        float4 acc[8];
        #pragma unroll
        for (int j = 0; j < 8; j++) acc[j] = make_float4(0.f, 0.f, 0.f, 0.f);
        #pragma unroll
        for (int g = 0; g < 32; g++) {
            float a = ss[lane*33 + g];
            const float* vr = sv + g*RS + w*32;
            #pragma unroll
            for (int j = 0; j < 8; j++) {
                float4 v4 = *(const float4*)(vr + j*4);
                acc[j].x += a*v4.x; acc[j].y += a*v4.y;
                acc[j].z += a*v4.z; acc[j].w += a*v4.w;
            }
        }
        float* dst = attn + (size_t)b * CDIM;
        #pragma unroll
        for (int j = 0; j < 8; j++) {
            int d0 = w*32 + j*4;
            dst[(d0+0)*32 + lane] = acc[j].x;
            dst[(d0+1)*32 + lane] = acc[j].y;
            dst[(d0+2)*32 + lane] = acc[j].z;
            dst[(d0+3)*32 + lane] = acc[j].w;
        }
    }
}

extern "C" void kernel_launch(void* const* d_in, const int* in_sizes, int n_in,
                              void* d_out, int out_size)
{
    const float* x      = (const float*)d_in[0];
    const float* w_qkv  = (const float*)d_in[1];
    const float* w_proj = (const float*)d_in[2];
    const float* b_proj = (const float*)d_in[3];
    float* out = (float*)d_out;

    float *qkv, *attn;
    cudaGetSymbolAddress((void**)&qkv, g_qkv);
    cudaGetSymbolAddress((void**)&attn, g_attn);

    cudaFuncSetAttribute(attn_kernel, cudaFuncAttributeMaxDynamicSharedMemorySize, 55296);

    gemm_tf32<<<dim3(96, 64), 256>>>(x, w_qkv, qkv, nullptr, NQKV);
    attn_kernel<<<BDIM, 128, 55296>>>(qkv, attn);
    gemm_tf32<<<dim3(32, 64), 256>>>(attn, w_proj, out, b_proj, CDIM);
}

// round 7
// speedup vs baseline: 1.1130x; 1.1130x over previous
#include <cuda_runtime.h>
#include <cstdint>
#include <cstddef>

#define BDIM 8192
#define CDIM 4096
#define NQKV 12288

__device__ __align__(1024) float g_x [(size_t)BDIM * CDIM];
__device__ __align__(1024) float g_wq[(size_t)NQKV * CDIM];
__device__ __align__(1024) float g_wp[(size_t)CDIM * CDIM];
__device__ __align__(1024) float g_qkv[(size_t)BDIM * NQKV];
__device__ __align__(1024) float g_attn[(size_t)BDIM * CDIM];

__device__ __forceinline__ uint32_t smem_u32(const void* p) {
    uint32_t a;
    asm("{ .reg .u64 t; cvta.to.shared.u64 t, %1; cvt.u32.u64 %0, t; }" : "=r"(a) : "l"(p));
    return a;
}
__device__ __forceinline__ float rna(float x) {
    uint32_t u; asm("cvt.rna.tf32.f32 %0, %1;" : "=r"(u) : "f"(x));
    return __uint_as_float(u);
}
__device__ __forceinline__ void mma8(float* c, const uint32_t* a, const uint32_t* b) {
    asm volatile("mma.sync.aligned.m16n8k8.row.col.f32.tf32.tf32.f32 "
        "{%0,%1,%2,%3}, {%4,%5,%6,%7}, {%8,%9}, {%0,%1,%2,%3};"
        : "+f"(c[0]), "+f"(c[1]), "+f"(c[2]), "+f"(c[3])
        : "r"(a[0]), "r"(a[1]), "r"(a[2]), "r"(a[3]), "r"(b[0]), "r"(b[1]));
}
__device__ __forceinline__ void cpasync16(uint32_t dst, const float* src) {
    asm volatile("cp.async.cg.shared.global [%0], [%1], 16;" :: "r"(dst), "l"(src));
}
#define CP_COMMIT asm volatile("cp.async.commit_group;" ::: "memory")
#define CP_WAIT1  asm volatile("cp.async.wait_group 1;" ::: "memory")

// tf32 pre-rounding pass
__global__ void __launch_bounds__(256) cvt_k(float* __restrict__ d, const float* __restrict__ s, int n4) {
    int i = blockIdx.x * blockDim.x + threadIdx.x, st = gridDim.x * blockDim.x;
    const float4* s4 = (const float4*)s;
    float4* d4 = (float4*)d;
    for (; i < n4; i += st) {
        float4 v = s4[i];
        v.x = rna(v.x); v.y = rna(v.y); v.z = rna(v.z); v.w = rna(v.w);
        d4[i] = v;
    }
}

// C[m,n] = sum_k A[m,k]*B[n,k] (+bias[n]); A,B K-major, pre-rounded tf32. K=4096.
// 128x128 tile, 256 thr, 8 warps of 64x32, 3-stage cp.async (BK=16).
#define SSTG 5120   // floats per stage: (128*20)*2
__global__ void __launch_bounds__(256) gemm_tf32(
    const float* __restrict__ A, const float* __restrict__ B,
    float* __restrict__ C, const float* __restrict__ bias, int ntot)
{
    extern __shared__ __align__(16) float smf[];
    const int tid = threadIdx.x, lane = tid & 31, wid = tid >> 5;
    const int gid = lane >> 2, tig = lane & 3;
    const int wm = wid & 1, wn = wid >> 1;

    // stripe rasterization: 8 n-tiles wide -> wave working set fits L2
    const int tn = gridDim.x, tm = gridDim.y;
    const int lin = blockIdx.y * tn + blockIdx.x;
    const int GN = 8;
    const int stripe = lin / (tm * GN), rem = lin - stripe * (tm * GN);
    const int width = min(GN, tn - stripe * GN);
    const int n0 = (stripe * GN + rem % width) * 128;
    const int m0 = (rem / width) * 128;

    float acc[4][4][4] = {};
    const uint32_t sb = smem_u32(smf);

    // issue loads for stage buffer sidx, k-tile kt
    auto issue = [&](int sidx, int kt) {
        uint32_t da = sb + sidx * SSTG * 4, db = da + 2560 * 4;
        #pragma unroll
        for (int i = tid; i < 512; i += 256) {
            int r = i >> 2, c = i & 3;
            cpasync16(da + (r * 20 + c * 4) * 4, A + (size_t)(m0 + r) * 4096 + kt * 16 + c * 4);
            cpasync16(db + (r * 20 + c * 4) * 4, B + (size_t)(n0 + r) * 4096 + kt * 16 + c * 4);
        }
    };

    issue(0, 0); CP_COMMIT;
    issue(1, 1); CP_COMMIT;

    int buf = 0;
    #pragma unroll 1
    for (int kt = 0; kt < 256; kt++) {
        CP_WAIT1;
        __syncthreads();
        // prefetch kt+2 into buffer (buf+2)%3; commit unconditionally to keep
        // the wait_group accounting invariant through the tail.
        int nb = buf + 2; if (nb >= 3) nb -= 3;
        if (kt + 2 < 256) issue(nb, kt + 2);
        CP_COMMIT;

        const float* As = smf + buf * SSTG;
        const float* Bs = As + 2560;
        #pragma unroll
        for (int ks = 0; ks < 2; ks++) {
            const int k = ks * 8;
            uint32_t a[4][4], bf[4][2];
            #pragma unroll
            for (int mt = 0; mt < 4; mt++) {
                int r = wm * 64 + mt * 16 + gid;
                a[mt][0] = __float_as_uint(As[r * 20 + k + tig]);
                a[mt][1] = __float_as_uint(As[(r + 8) * 20 + k + tig]);
                a[mt][2] = __float_as_uint(As[r * 20 + k + tig + 4]);
                a[mt][3] = __float_as_uint(As[(r + 8) * 20 + k + tig + 4]);
            }
            #pragma unroll
            for (int nt = 0; nt < 4; nt++) {
                int n = wn * 32 + nt * 8 + gid;
                bf[nt][0] = __float_as_uint(Bs[n * 20 + k + tig]);
                bf[nt][1] = __float_as_uint(Bs[n * 20 + k + tig + 4]);
            }
            #pragma unroll
            for (int mt = 0; mt < 4; mt++)
                #pragma unroll
                for (int nt = 0; nt < 4; nt++)
                    mma8(acc[mt][nt], a[mt], bf[nt]);
        }
        if (++buf == 3) buf = 0;
    }

    #pragma unroll
    for (int mt = 0; mt < 4; mt++) {
        #pragma unroll
        for (int nt = 0; nt < 4; nt++) {
            int row = m0 + wm * 64 + mt * 16 + gid;
            int col = n0 + wn * 32 + nt * 8 + tig * 2;
            float b0 = 0.f, b1 = 0.f;
            if (bias) { b0 = bias[col]; b1 = bias[col + 1]; }
            *(float2*)(C + (size_t)row * ntot + col) =
                make_float2(acc[mt][nt][0] + b0, acc[mt][nt][1] + b1);
            *(float2*)(C + (size_t)(row + 8) * ntot + col) =
                make_float2(acc[mt][nt][2] + b0, acc[mt][nt][3] + b1);
        }
    }
}

// per-token 32x32 head-mixing attention; out col = d*32+h, stored tf32-rounded
#define RS 132
__global__ void __launch_bounds__(128) attn_kernel(
    const float* __restrict__ qkv, float* __restrict__ attn)
{
    extern __shared__ float sm[];
    const int b = blockIdx.x, t = threadIdx.x, w = t >> 5, lane = t & 31;

    const float4* src4 = (const float4*)(qkv + (size_t)b * NQKV);
    for (int i = t; i < 3072; i += 128) {
        int mat = i >> 10, rm = i & 1023;
        *(float4*)(sm + mat * (32 * RS) + (rm >> 5) * RS + (rm & 31) * 4) = src4[i];
    }
    __syncthreads();

    float* sq = sm;
    float* sk = sm + 32 * RS;
    float* sv = sm + 64 * RS;
    float* ss = sm + 96 * RS;
    const float scale = 0.08838834764831845f;

    {
        float a8[8] = {};
        #pragma unroll
        for (int ch = 0; ch < 4; ch++) {
            float4 q[8];
            #pragma unroll
            for (int j = 0; j < 8; j++)
                q[j] = *(const float4*)(sq + lane * RS + ch * 32 + j * 4);
            #pragma unroll
            for (int g0 = 0; g0 < 8; g0++) {
                const float* kr = sk + (w * 8 + g0) * RS + ch * 32;
                #pragma unroll
                for (int j = 0; j < 8; j++) {
                    float4 k4 = *(const float4*)(kr + j * 4);
                    a8[g0] += q[j].x * k4.x + q[j].y * k4.y + q[j].z * k4.z + q[j].w * k4.w;
                }
            }
        }
        #pragma unroll
        for (int g0 = 0; g0 < 8; g0++) ss[lane * 33 + w * 8 + g0] = a8[g0] * scale;
    }
    __syncthreads();

    if (w == 0) {
        float mx = -1e30f;
        #pragma unroll
        for (int g = 0; g < 32; g++) mx = fmaxf(mx, ss[lane * 33 + g]);
        float sum = 0.f;
        #pragma unroll
        for (int g = 0; g < 32; g++) {
            float e = __expf(ss[lane * 33 + g] - mx);
            ss[lane * 33 + g] = e; sum += e;
        }
        float inv = 1.f / sum;
        #pragma unroll
        for (int g = 0; g < 32; g++) ss[lane * 33 + g] *= inv;
    }
    __syncthreads();

    {
        float4 acc[8];
        #pragma unroll
        for (int j = 0; j < 8; j++) acc[j] = make_float4(0.f, 0.f, 0.f, 0.f);
        #pragma unroll
        for (int g = 0; g < 32; g++) {
            float a = ss[lane * 33 + g];
            const float* vr = sv + g * RS + w * 32;
            #pragma unroll
            for (int j = 0; j < 8; j++) {
                float4 v4 = *(const float4*)(vr + j * 4);
                acc[j].x += a * v4.x; acc[j].y += a * v4.y;
                acc[j].z += a * v4.z; acc[j].w += a * v4.w;
            }
        }
        float* dst = attn + (size_t)b * CDIM;
        #pragma unroll
        for (int j = 0; j < 8; j++) {
            int d0 = w * 32 + j * 4;
            dst[(d0 + 0) * 32 + lane] = rna(acc[j].x);
            dst[(d0 + 1) * 32 + lane] = rna(acc[j].y);
            dst[(d0 + 2) * 32 + lane] = rna(acc[j].z);
            dst[(d0 + 3) * 32 + lane] = rna(acc[j].w);
        }
    }
}

extern "C" void kernel_launch(void* const* d_in, const int* in_sizes, int n_in,
                              void* d_out, int out_size)
{
    const float* x  = (const float*)d_in[0];
    const float* wq = (const float*)d_in[1];
    const float* wp = (const float*)d_in[2];
    const float* bp = (const float*)d_in[3];
    float* out = (float*)d_out;

    float *gx, *gwq, *gwp, *qkv, *attn;
    cudaGetSymbolAddress((void**)&gx, g_x);
    cudaGetSymbolAddress((void**)&gwq, g_wq);
    cudaGetSymbolAddress((void**)&gwp, g_wp);
    cudaGetSymbolAddress((void**)&qkv, g_qkv);
    cudaGetSymbolAddress((void**)&attn, g_attn);

    cudaFuncSetAttribute(gemm_tf32, cudaFuncAttributeMaxDynamicSharedMemorySize, 3 * SSTG * 4);
    cudaFuncSetAttribute(attn_kernel, cudaFuncAttributeMaxDynamicSharedMemorySize, 55296);

    cvt_k<<<512, 256>>>(gx, x, (int)((size_t)BDIM * CDIM / 4));
    cvt_k<<<512, 256>>>(gwq, wq, (int)((size_t)NQKV * CDIM / 4));
    cvt_k<<<512, 256>>>(gwp, wp, (int)((size_t)CDIM * CDIM / 4));
    gemm_tf32<<<dim3(96, 64), 256, 3 * SSTG * 4>>>(gx, gwq, qkv, nullptr, NQKV);
    attn_kernel<<<BDIM, 128, 55296>>>(qkv, attn);
    gemm_tf32<<<dim3(32, 64), 256, 3 * SSTG * 4>>>(attn, gwp, out, bp, CDIM);
}

// round 9
// speedup vs baseline: 1.1758x; 1.0563x over previous
#include <cuda_runtime.h>
#include <cstdint>
#include <cstddef>

#define BDIM 8192
#define CDIM 4096
#define NQKV 12288

__device__ __align__(1024) float g_x [(size_t)BDIM * CDIM];
__device__ __align__(1024) float g_wq[(size_t)NQKV * CDIM];
__device__ __align__(1024) float g_wp[(size_t)CDIM * CDIM];
__device__ __align__(1024) float g_qkv[(size_t)BDIM * NQKV];
__device__ __align__(1024) float g_attn[(size_t)BDIM * CDIM];

__device__ __forceinline__ uint32_t smem_u32(const void* p) {
    uint32_t a;
    asm("{ .reg .u64 t; cvta.to.shared.u64 t, %1; cvt.u32.u64 %0, t; }" : "=r"(a) : "l"(p));
    return a;
}
__device__ __forceinline__ float rna(float x) {
    uint32_t u; asm("cvt.rna.tf32.f32 %0, %1;" : "=r"(u) : "f"(x));
    return __uint_as_float(u);
}
__device__ __forceinline__ void mma8(float* c, const uint32_t* a, const uint32_t* b) {
    asm volatile("mma.sync.aligned.m16n8k8.row.col.f32.tf32.tf32.f32 "
        "{%0,%1,%2,%3}, {%4,%5,%6,%7}, {%8,%9}, {%0,%1,%2,%3};"
        : "+f"(c[0]), "+f"(c[1]), "+f"(c[2]), "+f"(c[3])
        : "r"(a[0]), "r"(a[1]), "r"(a[2]), "r"(a[3]), "r"(b[0]), "r"(b[1]));
}
__device__ __forceinline__ void cpasync16(uint32_t dst, const float* src) {
    asm volatile("cp.async.cg.shared.global [%0], [%1], 16;" :: "r"(dst), "l"(src));
}
#define CP_COMMIT asm volatile("cp.async.commit_group;" ::: "memory")
#define CP_WAIT2  asm volatile("cp.async.wait_group 2;" ::: "memory")

// tf32 pre-round + k-permute (within each 8-group store order [0,4,1,5,2,6,3,7]).
// Each thread handles one 8-float group: fully coalesced float4 both ways.
__global__ void __launch_bounds__(256) cvt_k(float* __restrict__ d, const float* __restrict__ s, int n8) {
    int i = blockIdx.x * blockDim.x + threadIdx.x, st = gridDim.x * blockDim.x;
    const float4* s4 = (const float4*)s;
    float4* d4 = (float4*)d;
    for (; i < n8; i += st) {
        float4 v0 = s4[2 * i], v1 = s4[2 * i + 1];
        float4 o0, o1;
        o0.x = rna(v0.x); o0.y = rna(v1.x); o0.z = rna(v0.y); o0.w = rna(v1.y);
        o1.x = rna(v0.z); o1.y = rna(v1.z); o1.z = rna(v0.w); o1.w = rna(v1.w);
        d4[2 * i] = o0; d4[2 * i + 1] = o1;
    }
}

// C[m,n] = sum_k A[m,k]*B[n,k] (+bias[n]); A,B K-major k-PERMUTED tf32. K=4096.
// 128x128 tile, 256 thr, 8 warps (64x32), BK=16, 4-stage cp.async, LDS.64 frags.
#define RSTR 24                       // smem row stride (floats): conflict-free LDS.64
#define SSTG (128 * RSTR * 2)         // floats per stage (A + B)
#define NSTG 4
__global__ void __launch_bounds__(256) gemm_tf32(
    const float* __restrict__ A, const float* __restrict__ B,
    float* __restrict__ C, const float* __restrict__ bias, int ntot)
{
    extern __shared__ __align__(16) float smf[];
    const int tid = threadIdx.x, lane = tid & 31, wid = tid >> 5;
    const int gid = lane >> 2, tig = lane & 3;
    const int wm = wid & 1, wn = wid >> 1;

    const int tn = gridDim.x, tm = gridDim.y;
    const int lin = blockIdx.y * tn + blockIdx.x;
    const int GN = 8;
    const int stripe = lin / (tm * GN), rem = lin - stripe * (tm * GN);
    const int width = min(GN, tn - stripe * GN);
    const int n0 = (stripe * GN + rem % width) * 128;
    const int m0 = (rem / width) * 128;

    float acc[4][4][4] = {};
    const uint32_t sb = smem_u32(smf);

    auto issue = [&](int sidx, int kt) {
        uint32_t da = sb + sidx * SSTG * 4, db = da + 128 * RSTR * 4;
        #pragma unroll
        for (int i = tid; i < 512; i += 256) {
            int r = i >> 2, c = i & 3;
            cpasync16(da + (r * RSTR + c * 4) * 4, A + (size_t)(m0 + r) * 4096 + kt * 16 + c * 4);
            cpasync16(db + (r * RSTR + c * 4) * 4, B + (size_t)(n0 + r) * 4096 + kt * 16 + c * 4);
        }
    };

    issue(0, 0); CP_COMMIT;
    issue(1, 1); CP_COMMIT;
    issue(2, 2); CP_COMMIT;

    int buf = 0;
    #pragma unroll 1
    for (int kt = 0; kt < 256; kt++) {
        CP_WAIT2;
        __syncthreads();
        int nb = buf + 3; if (nb >= NSTG) nb -= NSTG;
        if (kt + 3 < 256) issue(nb, kt + 3);
        CP_COMMIT;

        const float* As = smf + buf * SSTG;
        const float* Bs = As + 128 * RSTR;
        #pragma unroll
        for (int ks = 0; ks < 2; ks++) {
            const int k8 = ks * 8 + tig * 2;
            uint32_t a[4][4], bf[4][2];
            #pragma unroll
            for (int mt = 0; mt < 4; mt++) {
                int r = wm * 64 + mt * 16 + gid;
                float2 lo = *(const float2*)(As + r * RSTR + k8);        // (k+tig, k+tig+4)
                float2 hi = *(const float2*)(As + (r + 8) * RSTR + k8);
                a[mt][0] = __float_as_uint(lo.x); a[mt][1] = __float_as_uint(hi.x);
                a[mt][2] = __float_as_uint(lo.y); a[mt][3] = __float_as_uint(hi.y);
            }
            #pragma unroll
            for (int nt = 0; nt < 4; nt++) {
                int n = wn * 32 + nt * 8 + gid;
                float2 bb = *(const float2*)(Bs + n * RSTR + k8);
                bf[nt][0] = __float_as_uint(bb.x); bf[nt][1] = __float_as_uint(bb.y);
            }
            #pragma unroll
            for (int mt = 0; mt < 4; mt++)
                #pragma unroll
                for (int nt = 0; nt < 4; nt++)
                    mma8(acc[mt][nt], a[mt], bf[nt]);
        }
        if (++buf == NSTG) buf = 0;
    }

    #pragma unroll
    for (int mt = 0; mt < 4; mt++) {
        #pragma unroll
        for (int nt = 0; nt < 4; nt++) {
            int row = m0 + wm * 64 + mt * 16 + gid;
            int col = n0 + wn * 32 + nt * 8 + tig * 2;
            float b0 = 0.f, b1 = 0.f;
            if (bias) { b0 = bias[col]; b1 = bias[col + 1]; }
            *(float2*)(C + (size_t)row * ntot + col) =
                make_float2(acc[mt][nt][0] + b0, acc[mt][nt][1] + b1);
            *(float2*)(C + (size_t)(row + 8) * ntot + col) =
                make_float2(acc[mt][nt][2] + b0, acc[mt][nt][3] + b1);
        }
    }
}

// per-token 32x32 head-mixing attention; out col = d*32+h, tf32-rounded,
// stored k-PERMUTED (feeds gemm2 A): permute applies to lane (= h) bits.
#define RS 132
__global__ void __launch_bounds__(128) attn_kernel(
    const float* __restrict__ qkv, float* __restrict__ attn)
{
    extern __shared__ float sm[];
    const int b = blockIdx.x, t = threadIdx.x, w = t >> 5, lane = t & 31;

    const float4* src4 = (const float4*)(qkv + (size_t)b * NQKV);
    for (int i = t; i < 3072; i += 128) {
        int mat = i >> 10, rm = i & 1023;
        *(float4*)(sm + mat * (32 * RS) + (rm >> 5) * RS + (rm & 31) * 4) = src4[i];
    }
    __syncthreads();

    float* sq = sm;
    float* sk = sm + 32 * RS;
    float* sv = sm + 64 * RS;
    float* ss = sm + 96 * RS;
    const float scale = 0.08838834764831845f;

    {
        float a8[8] = {};
        #pragma unroll
        for (int ch = 0; ch < 4; ch++) {
            float4 q[8];
            #pragma unroll
            for (int j = 0; j < 8; j++)
                q[j] = *(const float4*)(sq + lane * RS + ch * 32 + j * 4);
            #pragma unroll
            for (int g0 = 0; g0 < 8; g0++) {
                const float* kr = sk + (w * 8 + g0) * RS + ch * 32;
                #pragma unroll
                for (int j = 0; j < 8; j++) {
                    float4 k4 = *(const float4*)(kr + j * 4);
                    a8[g0] += q[j].x * k4.x + q[j].y * k4.y + q[j].z * k4.z + q[j].w * k4.w;
                }
            }
        }
        #pragma unroll
        for (int g0 = 0; g0 < 8; g0++) ss[lane * 33 + w * 8 + g0] = a8[g0] * scale;
    }
    __syncthreads();

    if (w == 0) {
        float mx = -1e30f;
        #pragma unroll
        for (int g = 0; g < 32; g++) mx = fmaxf(mx, ss[lane * 33 + g]);
        float sum = 0.f;
        #pragma unroll
        for (int g = 0; g < 32; g++) {
            float e = __expf(ss[lane * 33 + g] - mx);
            ss[lane * 33 + g] = e; sum += e;
        }
        float inv = 1.f / sum;
        #pragma unroll
        for (int g = 0; g < 32; g++) ss[lane * 33 + g] *= inv;
    }
    __syncthreads();

    {
        float4 acc[8];
        #pragma unroll
        for (int j = 0; j < 8; j++) acc[j] = make_float4(0.f, 0.f, 0.f, 0.f);
        #pragma unroll
        for (int g = 0; g < 32; g++) {
            float a = ss[lane * 33 + g];
            const float* vr = sv + g * RS + w * 32;
            #pragma unroll
            for (int j = 0; j < 8; j++) {
                float4 v4 = *(const float4*)(vr + j * 4);
                acc[j].x += a * v4.x; acc[j].y += a * v4.y;
                acc[j].z += a * v4.z; acc[j].w += a * v4.w;
            }
        }
        // permuted column index: col = d*32 + h; col%8 depends only on h=lane
        const int plane = (lane & 24) | ((lane & 3) << 1) | ((lane >> 2) & 1);
        float* dst = attn + (size_t)b * CDIM;
        #pragma unroll
        for (int j = 0; j < 8; j++) {
            int d0 = w * 32 + j * 4;
            dst[(d0 + 0) * 32 + plane] = rna(acc[j].x);
            dst[(d0 + 1) * 32 + plane] = rna(acc[j].y);
            dst[(d0 + 2) * 32 + plane] = rna(acc[j].z);
            dst[(d0 + 3) * 32 + plane] = rna(acc[j].w);
        }
    }
}

extern "C" void kernel_launch(void* const* d_in, const int* in_sizes, int n_in,
                              void* d_out, int out_size)
{
    const float* x  = (const float*)d_in[0];
    const float* wq = (const float*)d_in[1];
    const float* wp = (const float*)d_in[2];
    const float* bp = (const float*)d_in[3];
    float* out = (float*)d_out;

    float *gx, *gwq, *gwp, *qkv, *attn;
    cudaGetSymbolAddress((void**)&gx, g_x);
    cudaGetSymbolAddress((void**)&gwq, g_wq);
    cudaGetSymbolAddress((void**)&gwp, g_wp);
    cudaGetSymbolAddress((void**)&qkv, g_qkv);
    cudaGetSymbolAddress((void**)&attn, g_attn);

    cudaFuncSetAttribute(gemm_tf32, cudaFuncAttributeMaxDynamicSharedMemorySize, NSTG * SSTG * 4);
    cudaFuncSetAttribute(attn_kernel, cudaFuncAttributeMaxDynamicSharedMemorySize, 55296);

    cvt_k<<<512, 256>>>(gx, x, (int)((size_t)BDIM * CDIM / 8));
    cvt_k<<<512, 256>>>(gwq, wq, (int)((size_t)NQKV * CDIM / 8));
    cvt_k<<<512, 256>>>(gwp, wp, (int)((size_t)CDIM * CDIM / 8));
    gemm_tf32<<<dim3(96, 64), 256, NSTG * SSTG * 4>>>(gx, gwq, qkv, nullptr, NQKV);
    attn_kernel<<<BDIM, 128, 55296>>>(qkv, attn);
    gemm_tf32<<<dim3(32, 64), 256, NSTG * SSTG * 4>>>(attn, gwp, out, bp, CDIM);
}

// round 10
// speedup vs baseline: 1.4169x; 1.2051x over previous
#include <cuda_runtime.h>
#include <cstdint>
#include <cstddef>

#define BDIM 8192
#define CDIM 4096
#define NQKV 12288

__device__ __align__(1024) float g_x [(size_t)BDIM * CDIM];
__device__ __align__(1024) float g_wq[(size_t)NQKV * CDIM];
__device__ __align__(1024) float g_wp[(size_t)CDIM * CDIM];
__device__ __align__(1024) float g_qkv[(size_t)BDIM * NQKV];
__device__ __align__(1024) float g_attn[(size_t)BDIM * CDIM];

__device__ __forceinline__ uint32_t smem_u32(const void* p) {
    uint32_t a;
    asm("{ .reg .u64 t; cvta.to.shared.u64 t, %1; cvt.u32.u64 %0, t; }" : "=r"(a) : "l"(p));
    return a;
}
__device__ __forceinline__ float rna(float x) {
    uint32_t u; asm("cvt.rna.tf32.f32 %0, %1;" : "=r"(u) : "f"(x));
    return __uint_as_float(u);
}
__device__ __forceinline__ void mma8(float* c, const uint32_t* a, const uint32_t* b) {
    asm volatile("mma.sync.aligned.m16n8k8.row.col.f32.tf32.tf32.f32 "
        "{%0,%1,%2,%3}, {%4,%5,%6,%7}, {%8,%9}, {%0,%1,%2,%3};"
        : "+f"(c[0]), "+f"(c[1]), "+f"(c[2]), "+f"(c[3])
        : "r"(a[0]), "r"(a[1]), "r"(a[2]), "r"(a[3]), "r"(b[0]), "r"(b[1]));
}
__device__ __forceinline__ void cpasync16(uint32_t dst, const float* src) {
    asm volatile("cp.async.cg.shared.global [%0], [%1], 16;" :: "r"(dst), "l"(src));
}
#define CP_COMMIT asm volatile("cp.async.commit_group;" ::: "memory")
#define CP_WAIT2  asm volatile("cp.async.wait_group 2;" ::: "memory")

// tf32 pre-round + k-permute (within each 8-group store order [0,4,1,5,2,6,3,7])
__global__ void __launch_bounds__(256) cvt_k(float* __restrict__ d, const float* __restrict__ s, int n8) {
    int i = blockIdx.x * blockDim.x + threadIdx.x, st = gridDim.x * blockDim.x;
    const float4* s4 = (const float4*)s;
    float4* d4 = (float4*)d;
    for (; i < n8; i += st) {
        float4 v0 = s4[2 * i], v1 = s4[2 * i + 1];
        float4 o0, o1;
        o0.x = rna(v0.x); o0.y = rna(v1.x); o0.z = rna(v0.y); o0.w = rna(v1.y);
        o1.x = rna(v0.z); o1.y = rna(v1.z); o1.z = rna(v0.w); o1.w = rna(v1.w);
        d4[2 * i] = o0; d4[2 * i + 1] = o1;
    }
}

// C[m,n] = sum_k A[m,k]*B[n,k] (+bias[n]); A,B K-major k-PERMUTED tf32. K=4096.
// 128x128 tile, 128 thr, 4 warps of 64x64, BK=16, 4-stage cp.async, LDS.64 frags.
#define RSTR 24
#define SSTG (128 * RSTR * 2)
#define NSTG 4
__global__ void __launch_bounds__(128, 2) gemm_tf32(
    const float* __restrict__ A, const float* __restrict__ B,
    float* __restrict__ C, const float* __restrict__ bias, int ntot)
{
    extern __shared__ __align__(16) float smf[];
    const int tid = threadIdx.x, lane = tid & 31, wid = tid >> 5;
    const int gid = lane >> 2, tig = lane & 3;
    const int wm = wid & 1, wn = wid >> 1;       // 2x2 warp grid, 64x64 each

    const int tn = gridDim.x, tm = gridDim.y;
    const int lin = blockIdx.y * tn + blockIdx.x;
    const int GN = 8;
    const int stripe = lin / (tm * GN), rem = lin - stripe * (tm * GN);
    const int width = min(GN, tn - stripe * GN);
    const int n0 = (stripe * GN + rem % width) * 128;
    const int m0 = (rem / width) * 128;

    float acc[4][8][4] = {};
    const uint32_t sb = smem_u32(smf);

    auto issue = [&](int sidx, int kt) {
        uint32_t da = sb + sidx * SSTG * 4, db = da + 128 * RSTR * 4;
        #pragma unroll
        for (int i = tid; i < 512; i += 128) {
            int r = i >> 2, c = i & 3;
            cpasync16(da + (r * RSTR + c * 4) * 4, A + (size_t)(m0 + r) * 4096 + kt * 16 + c * 4);
            cpasync16(db + (r * RSTR + c * 4) * 4, B + (size_t)(n0 + r) * 4096 + kt * 16 + c * 4);
        }
    };

    issue(0, 0); CP_COMMIT;
    issue(1, 1); CP_COMMIT;
    issue(2, 2); CP_COMMIT;

    int buf = 0;
    #pragma unroll 1
    for (int kt = 0; kt < 256; kt++) {
        CP_WAIT2;
        __syncthreads();
        int nb = buf + 3; if (nb >= NSTG) nb -= NSTG;
        if (kt + 3 < 256) issue(nb, kt + 3);
        CP_COMMIT;

        const float* As = smf + buf * SSTG + (wm * 64 + gid) * RSTR;
        const float* Bs = smf + buf * SSTG + 128 * RSTR + (wn * 64 + gid) * RSTR;
        #pragma unroll
        for (int ks = 0; ks < 2; ks++) {
            const int k8 = ks * 8 + tig * 2;
            uint32_t a[4][4], bf[8][2];
            #pragma unroll
            for (int mt = 0; mt < 4; mt++) {
                float2 lo = *(const float2*)(As + mt * 16 * RSTR + k8);       // (k+tig, k+tig+4)
                float2 hi = *(const float2*)(As + (mt * 16 + 8) * RSTR + k8);
                a[mt][0] = __float_as_uint(lo.x); a[mt][1] = __float_as_uint(hi.x);
                a[mt][2] = __float_as_uint(lo.y); a[mt][3] = __float_as_uint(hi.y);
            }
            #pragma unroll
            for (int nt = 0; nt < 8; nt++) {
                float2 bb = *(const float2*)(Bs + nt * 8 * RSTR + k8);
                bf[nt][0] = __float_as_uint(bb.x); bf[nt][1] = __float_as_uint(bb.y);
            }
            #pragma unroll
            for (int mt = 0; mt < 4; mt++)
                #pragma unroll
                for (int nt = 0; nt < 8; nt++)
                    mma8(acc[mt][nt], a[mt], bf[nt]);
        }
        if (++buf == NSTG) buf = 0;
    }

    #pragma unroll
    for (int mt = 0; mt < 4; mt++) {
        #pragma unroll
        for (int nt = 0; nt < 8; nt++) {
            int row = m0 + wm * 64 + mt * 16 + gid;
            int col = n0 + wn * 64 + nt * 8 + tig * 2;
            float b0 = 0.f, b1 = 0.f;
            if (bias) { b0 = bias[col]; b1 = bias[col + 1]; }
            *(float2*)(C + (size_t)row * ntot + col) =
                make_float2(acc[mt][nt][0] + b0, acc[mt][nt][1] + b1);
            *(float2*)(C + (size_t)(row + 8) * ntot + col) =
                make_float2(acc[mt][nt][2] + b0, acc[mt][nt][3] + b1);
        }
    }
}

// per-token 32x32 head-mixing attention; out col = d*32+h, tf32-rounded,
// stored k-PERMUTED (feeds gemm2 A); permute acts on lane (= h) bits.
#define RS 132
__global__ void __launch_bounds__(128) attn_kernel(
    const float* __restrict__ qkv, float* __restrict__ attn)
{
    extern __shared__ float sm[];
    const int b = blockIdx.x, t = threadIdx.x, w = t >> 5, lane = t & 31;

    const float4* src4 = (const float4*)(qkv + (size_t)b * NQKV);
    for (int i = t; i < 3072; i += 128) {
        int mat = i >> 10, rm = i & 1023;
        *(float4*)(sm + mat * (32 * RS) + (rm >> 5) * RS + (rm & 31) * 4) = src4[i];
    }
    __syncthreads();

    float* sq = sm;
    float* sk = sm + 32 * RS;
    float* sv = sm + 64 * RS;
    float* ss = sm + 96 * RS;
    const float scale = 0.08838834764831845f;

    {
        float a8[8] = {};
        #pragma unroll
        for (int ch = 0; ch < 4; ch++) {
            float4 q[8];
            #pragma unroll
            for (int j = 0; j < 8; j++)
                q[j] = *(const float4*)(sq + lane * RS + ch * 32 + j * 4);
            #pragma unroll
            for (int g0 = 0; g0 < 8; g0++) {
                const float* kr = sk + (w * 8 + g0) * RS + ch * 32;
                #pragma unroll
                for (int j = 0; j < 8; j++) {
                    float4 k4 = *(const float4*)(kr + j * 4);
                    a8[g0] += q[j].x * k4.x + q[j].y * k4.y + q[j].z * k4.z + q[j].w * k4.w;
                }
            }
        }
        #pragma unroll
        for (int g0 = 0; g0 < 8; g0++) ss[lane * 33 + w * 8 + g0] = a8[g0] * scale;
    }
    __syncthreads();

    if (w == 0) {
        float mx = -1e30f;
        #pragma unroll
        for (int g = 0; g < 32; g++) mx = fmaxf(mx, ss[lane * 33 + g]);
        float sum = 0.f;
        #pragma unroll
        for (int g = 0; g < 32; g++) {
            float e = __expf(ss[lane * 33 + g] - mx);
            ss[lane * 33 + g] = e; sum += e;
        }
        float inv = 1.f / sum;
        #pragma unroll
        for (int g = 0; g < 32; g++) ss[lane * 33 + g] *= inv;
    }
    __syncthreads();

    {
        float4 acc[8];
        #pragma unroll
        for (int j = 0; j < 8; j++) acc[j] = make_float4(0.f, 0.f, 0.f, 0.f);
        #pragma unroll
        for (int g = 0; g < 32; g++) {
            float a = ss[lane * 33 + g];
            const float* vr = sv + g * RS + w * 32;
            #pragma unroll
            for (int j = 0; j < 8; j++) {
                float4 v4 = *(const float4*)(vr + j * 4);
                acc[j].x += a * v4.x; acc[j].y += a * v4.y;
                acc[j].z += a * v4.z; acc[j].w += a * v4.w;
            }
        }
        const int plane = (lane & 24) | ((lane & 3) << 1) | ((lane >> 2) & 1);
        float* dst = attn + (size_t)b * CDIM;
        #pragma unroll
        for (int j = 0; j < 8; j++) {
            int d0 = w * 32 + j * 4;
            dst[(d0 + 0) * 32 + plane] = rna(acc[j].x);
            dst[(d0 + 1) * 32 + plane] = rna(acc[j].y);
            dst[(d0 + 2) * 32 + plane] = rna(acc[j].z);
            dst[(d0 + 3) * 32 + plane] = rna(acc[j].w);
        }
    }
}

extern "C" void kernel_launch(void* const* d_in, const int* in_sizes, int n_in,
                              void* d_out, int out_size)
{
    const float* x  = (const float*)d_in[0];
    const float* wq = (const float*)d_in[1];
    const float* wp = (const float*)d_in[2];
    const float* bp = (const float*)d_in[3];
    float* out = (float*)d_out;

    float *gx, *gwq, *gwp, *qkv, *attn;
    cudaGetSymbolAddress((void**)&gx, g_x);
    cudaGetSymbolAddress((void**)&gwq, g_wq);
    cudaGetSymbolAddress((void**)&gwp, g_wp);
    cudaGetSymbolAddress((void**)&qkv, g_qkv);
    cudaGetSymbolAddress((void**)&attn, g_attn);

    cudaFuncSetAttribute(gemm_tf32, cudaFuncAttributeMaxDynamicSharedMemorySize, NSTG * SSTG * 4);
    cudaFuncSetAttribute(attn_kernel, cudaFuncAttributeMaxDynamicSharedMemorySize, 55296);

    cvt_k<<<512, 256>>>(gx, x, (int)((size_t)BDIM * CDIM / 8));
    cvt_k<<<512, 256>>>(gwq, wq, (int)((size_t)NQKV * CDIM / 8));
    cvt_k<<<512, 256>>>(gwp, wp, (int)((size_t)CDIM * CDIM / 8));
    gemm_tf32<<<dim3(96, 64), 128, NSTG * SSTG * 4>>>(gx, gwq, qkv, nullptr, NQKV);
    attn_kernel<<<BDIM, 128, 55296>>>(qkv, attn);
    gemm_tf32<<<dim3(32, 64), 128, NSTG * SSTG * 4>>>(attn, gwp, out, bp, CDIM);
}